// round 7
// baseline (speedup 1.0000x reference)
#include <cuda_runtime.h>
#include <cstdint>

#define NB 64
#define NC 512
#define NHW 768
#define NT 32
#define NPROTO 4000
#define NCLASS 4001
#define GRID 128
#define TPB 256
#define BUFF 7392              // 112 rows * 66 floats per double-buffer half
#define SMEM_BYTES (2*BUFF*4)  // 59136 B

typedef unsigned long long ull;

// ---------------- scratch (device globals; no allocs allowed) ----------------
__device__ float g_C[NT * NB * NC];
__device__ float g_G[NB * 3072];
__device__ float g_h[NB * NC];
__device__ ull   g_amax[NB];
__device__ unsigned g_barcnt;    // returns to 0 after every completed barrier
__device__ unsigned g_barsense;  // monotonically increasing across launches

// ---------------- helpers ----------------
static __device__ __forceinline__ ull ffma2(ull a, ull b, ull c) {
    ull d;
    asm("fma.rn.f32x2 %0, %1, %2, %3;" : "=l"(d) : "l"(a), "l"(b), "l"(c));
    return d;
}
static __device__ __forceinline__ float fin(ull v) {
    float2 f = *(float2*)&v;
    return f.x + f.y;
}
// order-preserving float->uint packing; ties prefer lower index (argmax-first)
static __device__ __forceinline__ ull packkey(float s, int j) {
    unsigned u = __float_as_uint(s);
    u = (u & 0x80000000u) ? ~u : (u | 0x80000000u);
    return ((ull)u << 32) | (ull)(0xFFFFFFFFu - (unsigned)j);
}

// software grid barrier: release-arrive / acquire-spin, monotonic sense
static __device__ __forceinline__ void gridbar(unsigned& phase) {
    __syncthreads();
    if (threadIdx.x == 0) {
        phase += 1;
        unsigned old;
        asm volatile("atom.release.gpu.global.add.u32 %0,[%1],%2;"
                     : "=r"(old) : "l"(&g_barcnt), "r"(1u) : "memory");
        if (old == GRID - 1u) {
            g_barcnt = 0u;
            asm volatile("st.release.gpu.global.u32 [%0],%1;"
                         :: "l"(&g_barsense), "r"(phase) : "memory");
        } else {
            unsigned v;
            for (;;) {
                asm volatile("ld.acquire.gpu.global.u32 %0,[%1];"
                             : "=r"(v) : "l"(&g_barsense) : "memory");
                if (v == phase) break;
                __nanosleep(32);
            }
        }
    }
    __syncthreads();
}

extern __shared__ float S[];
#define XSM(bf,r,c) S[(bf)*BUFF + (r)*66 + (c)]           // 64-row region
#define WSM(bf,r,c) S[(bf)*BUFF + 4224 + (r)*66 + (c)]    // up-to-48-row region

// tile loaders -----------------------------------------------------------
#define ES_LOAD(bf, kc_) do { int kb = (kc_)*64;                                        \
    _Pragma("unroll") for (int i_ = 0; i_ < 8; ++i_) {                                  \
        int idx = tid + i_*256; int r = idx >> 6, cl = idx & 63;                        \
        WSM(bf, r, cl) = Ab[r * NHW + kb + cl]; }                                       \
    _Pragma("unroll") for (int i_ = 0; i_ < 16; ++i_) {                                 \
        int idx = tid + i_*256; int r = idx >> 6, cl = idx & 63;                        \
        XSM(bf, r, cl) = Fb[(size_t)r * NHW + kb + cl]; } } while (0)

#define GA_LOAD(bf, kc_) do { int kb = (kc_)*64;                                        \
    _Pragma("unroll") for (int i_ = 0; i_ < 16; ++i_) {                                 \
        int idx = tid + i_*256; int r = idx >> 6, cl = idx & 63; int k = kb + cl;       \
        XSM(bf, r, cl) = (k < 512) ? Ct[r * 512 + k] : prevp[r][k - 512]; }             \
    _Pragma("unroll") for (int i_ = 0; i_ < 4; ++i_) {                                  \
        int idx = tid + i_*256; int r = idx >> 6, cl = idx & 63;                        \
        WSM(bf, r, cl) = Wih[(size_t)(j0 + r) * 1024 + kb + cl]; } } while (0)

#define GB_LOAD(bf, kc_) do { int kb = (kc_)*64;                                        \
    _Pragma("unroll") for (int i_ = 0; i_ < 16; ++i_) {                                 \
        int idx = tid + i_*256; int r = idx >> 6, cl = idx & 63;                        \
        XSM(bf, r, cl) = g_h[r * 512 + kb + cl]; }                                      \
    _Pragma("unroll") for (int i_ = 0; i_ < 12; ++i_) {                                 \
        int idx = tid + i_*256; int r = idx >> 6, cl = idx & 63;                        \
        WSM(bf, r, cl) = Whh[(size_t)(j0 + r) * 512 + kb + cl]; } } while (0)

#define RW_LOAD(bf, kc_) do { int kb = (kc_)*64;                                        \
    _Pragma("unroll") for (int i_ = 0; i_ < 16; ++i_) {                                 \
        int idx = tid + i_*256; int r = idx >> 6, cl = idx & 63;                        \
        XSM(bf, r, cl) = g_h[r * 512 + kb + cl]; }                                      \
    _Pragma("unroll") for (int i_ = 0; i_ < 8; ++i_) {                                  \
        int idx = tid + i_*256; int r = idx >> 6, cl = idx & 63;                        \
        WSM(bf, r, cl) = protos[(size_t)(j0 + r) * 512 + kb + cl]; } } while (0)

__global__ __launch_bounds__(TPB)
void mega(const float* __restrict__ feat, const float* __restrict__ A,
          const float* __restrict__ protos, const float* __restrict__ semb,
          const float* __restrict__ sta, const float* __restrict__ unkv,
          const float* __restrict__ Wih, const float* __restrict__ Whh,
          const float* __restrict__ bih, const float* __restrict__ bhh,
          const float* __restrict__ alphap, const float* __restrict__ biasp,
          const float* __restrict__ unkscrp, float* __restrict__ out) {
    __shared__ const float* prevp[64];
    const int tid = threadIdx.x, bid = blockIdx.x;
    const int gid = bid * TPB + tid;               // 0..32767, exactly NB*NC
    unsigned phase = *(volatile unsigned*)&g_barsense;  // stable before 1st barrier

    const float alpha = *alphap, bias = *biasp, unkscr = *unkscrp;

    // ---------------- phase 0: init + out_attns copy + einsum ----------------
    g_h[gid] = 0.f;
    if (gid < NB) g_amax[gid] = (ull)(0xFFFFFFFFu - (unsigned)(NPROTO + 1)); // -> STA

    {   // copy A -> out_attns region
        const float4* A4 = (const float4*)A;
        float4* O4 = (float4*)(out + (size_t)NB * NT * NCLASS);
        for (int i = gid; i < NB * NT * NHW / 4; i += GRID * TPB) O4[i] = A4[i];
    }

    {   // einsum: 512 units of (32t x 64c), 4 per block
        const int ci = tid & 15, ti = tid >> 4;    // ci: c-group, ti: t-pair
        const int t2 = ti * 2;
        for (int u = bid; u < 512; u += GRID) {
            const int b = u & 63, c0 = (u >> 6) << 6;
            const float* Ab = A + (size_t)b * NT * NHW;
            const float* Fb = feat + (size_t)b * NC * NHW + (size_t)c0 * NHW;
            ull acc[2][4] = {};
            ES_LOAD(0, 0);
            __syncthreads();
#pragma unroll 2
            for (int kc = 0; kc < 12; ++kc) {
                int cur = kc & 1;
                if (kc < 11) ES_LOAD(cur ^ 1, kc + 1);
#pragma unroll 8
                for (int k2 = 0; k2 < 32; ++k2) {
                    ull a0 = *(const ull*)&WSM(cur, t2, 2 * k2);
                    ull a1 = *(const ull*)&WSM(cur, t2 + 1, 2 * k2);
#pragma unroll
                    for (int j = 0; j < 4; ++j) {
                        ull fv = *(const ull*)&XSM(cur, ci + 16 * j, 2 * k2);
                        acc[0][j] = ffma2(a0, fv, acc[0][j]);
                        acc[1][j] = ffma2(a1, fv, acc[1][j]);
                    }
                }
                __syncthreads();
            }
#pragma unroll
            for (int i = 0; i < 2; ++i)
#pragma unroll
                for (int j = 0; j < 4; ++j)
                    g_C[(t2 + i) * NB * NC + b * NC + c0 + ci + 16 * j] = fin(acc[i][j]);
            __syncthreads();
        }
    }
    gridbar(phase);

    // ---------------- time loop ----------------
    for (int t = 0; t < NT; ++t) {
        // ---- gates: 128 units (96 gi j-16 K1024 | 32 gh j-48 K512) ----
        if (tid < 64) {
            unsigned idx = 0xFFFFFFFFu - (unsigned)(g_amax[tid] & 0xFFFFFFFFull);
            prevp[tid] = (idx < NPROTO) ? (semb + (size_t)idx * NC)
                                        : ((idx == NPROTO) ? unkv : sta);
        }
        __syncthreads();
        const float* Ct = g_C + (size_t)t * NB * NC;

        if (bid < 96) {                       // gi: j0..j0+15, K=1024
            const int j0 = bid << 4;
            const int bi = tid & 31, ji = tid >> 5;   // ji uniform per warp -> bcast
            ull a00 = 0, a01 = 0, a10 = 0, a11 = 0;
            GA_LOAD(0, 0);
            __syncthreads();
#pragma unroll 2
            for (int kc = 0; kc < 16; ++kc) {
                int cur = kc & 1;
                if (kc < 15) GA_LOAD(cur ^ 1, kc + 1);
#pragma unroll 8
                for (int k2 = 0; k2 < 32; ++k2) {
                    ull w0 = *(const ull*)&WSM(cur, ji, 2 * k2);
                    ull w1 = *(const ull*)&WSM(cur, ji + 8, 2 * k2);
                    ull x0 = *(const ull*)&XSM(cur, bi, 2 * k2);
                    ull x1 = *(const ull*)&XSM(cur, bi + 32, 2 * k2);
                    a00 = ffma2(x0, w0, a00); a01 = ffma2(x0, w1, a01);
                    a10 = ffma2(x1, w0, a10); a11 = ffma2(x1, w1, a11);
                }
                __syncthreads();
            }
            g_G[bi * 3072 + j0 + ji]            = fin(a00);
            g_G[bi * 3072 + j0 + ji + 8]        = fin(a01);
            g_G[(bi + 32) * 3072 + j0 + ji]     = fin(a10);
            g_G[(bi + 32) * 3072 + j0 + ji + 8] = fin(a11);
        } else {                              // gh: j0..j0+47, K=512
            const int j0 = (bid - 96) * 48;
            const int bi = tid & 15, jq = tid >> 4;
            ull acc[4][3] = {};
            GB_LOAD(0, 0);
            __syncthreads();
#pragma unroll 2
            for (int kc = 0; kc < 8; ++kc) {
                int cur = kc & 1;
                if (kc < 7) GB_LOAD(cur ^ 1, kc + 1);
#pragma unroll 8
                for (int k2 = 0; k2 < 32; ++k2) {
                    ull wv0 = *(const ull*)&WSM(cur, jq, 2 * k2);
                    ull wv1 = *(const ull*)&WSM(cur, jq + 16, 2 * k2);
                    ull wv2 = *(const ull*)&WSM(cur, jq + 32, 2 * k2);
#pragma unroll
                    for (int i = 0; i < 4; ++i) {
                        ull hv = *(const ull*)&XSM(cur, bi + 16 * i, 2 * k2);
                        acc[i][0] = ffma2(hv, wv0, acc[i][0]);
                        acc[i][1] = ffma2(hv, wv1, acc[i][1]);
                        acc[i][2] = ffma2(hv, wv2, acc[i][2]);
                    }
                }
                __syncthreads();
            }
#pragma unroll
            for (int i = 0; i < 4; ++i)
#pragma unroll
                for (int j = 0; j < 3; ++j)
                    g_G[(bi + 16 * i) * 3072 + 1536 + j0 + jq + 16 * j] = fin(acc[i][j]);
        }
        gridbar(phase);

        // ---- GRU pointwise (fp64 transcendentals: fast-math-proof) ----
        {
            const int b = gid >> 9, c = gid & 511;
            const float* Gb = g_G + b * 3072;
            float ir = Gb[c]        + bih[c];
            float iz = Gb[512 + c]  + bih[512 + c];
            float inn = Gb[1024 + c] + bih[1024 + c];
            float hr = Gb[1536 + c] + bhh[c];
            float hz = Gb[2048 + c] + bhh[512 + c];
            float hn = Gb[2560 + c] + bhh[1024 + c];
            double r = 1.0 / (1.0 + exp(-(double)(ir + hr)));
            double z = 1.0 / (1.0 + exp(-(double)(iz + hz)));
            double n = tanh((double)inn + r * (double)hn);
            float hold = g_h[gid];
            g_h[gid] = (float)((1.0 - z) * n + z * (double)hold);
            if (gid < NB) g_amax[gid] = 0ull;          // reset for this step's argmax
        }
        gridbar(phase);

        // ---- raw scores + tens output + argmax: 125 units (j-tile 32, K=512) ----
        if (bid < 125) {
            const int j0 = bid * 32;
            const int ji = tid & 15, bi = tid >> 4;
            ull acc[4][2] = {};
            RW_LOAD(0, 0);
            __syncthreads();
#pragma unroll 2
            for (int kc = 0; kc < 8; ++kc) {
                int cur = kc & 1;
                if (kc < 7) RW_LOAD(cur ^ 1, kc + 1);
#pragma unroll 8
                for (int k2 = 0; k2 < 32; ++k2) {
                    ull p0 = *(const ull*)&WSM(cur, ji, 2 * k2);
                    ull p1 = *(const ull*)&WSM(cur, ji + 16, 2 * k2);
#pragma unroll
                    for (int i = 0; i < 4; ++i) {
                        ull hv = *(const ull*)&XSM(cur, bi + 16 * i, 2 * k2);
                        acc[i][0] = ffma2(hv, p0, acc[i][0]);
                        acc[i][1] = ffma2(hv, p1, acc[i][1]);
                    }
                }
                __syncthreads();
            }
            ull best[4];
#pragma unroll
            for (int i = 0; i < 4; ++i) {
                int b = bi + 16 * i;
                float s0 = fin(acc[i][0]) * alpha + bias;
                float s1 = fin(acc[i][1]) * alpha + bias;
                float* orow = out + ((size_t)b * NT + t) * NCLASS + j0;
                orow[ji] = s0;
                orow[ji + 16] = s1;
                ull k0 = packkey(s0, j0 + ji), k1 = packkey(s1, j0 + ji + 16);
                best[i] = (k0 > k1) ? k0 : k1;
            }
#pragma unroll
            for (int off = 8; off >= 1; off >>= 1)
#pragma unroll
                for (int i = 0; i < 4; ++i) {
                    ull o = __shfl_xor_sync(0xFFFFFFFFu, best[i], off);
                    if (o > best[i]) best[i] = o;
                }
            if (ji == 0)
#pragma unroll
                for (int i = 0; i < 4; ++i) atomicMax(&g_amax[bi + 16 * i], best[i]);
            if (bid == 0 && tid < NB) {   // UNK column
                out[((size_t)tid * NT + t) * NCLASS + NPROTO] = unkscr;
                atomicMax(&g_amax[tid], packkey(unkscr, NPROTO));
            }
        }
        gridbar(phase);
    }
}

// ---------------- launch ----------------
extern "C" void kernel_launch(void* const* d_in, const int* in_sizes, int n_in,
                              void* d_out, int out_size) {
    const float* feature = (const float*)d_in[0];
    const float* A       = (const float*)d_in[1];
    const float* protos  = (const float*)d_in[2];
    const float* semb    = (const float*)d_in[3];
    const float* sta     = (const float*)d_in[4];
    const float* unkv    = (const float*)d_in[5];
    const float* Wih     = (const float*)d_in[6];
    const float* Whh     = (const float*)d_in[7];
    const float* bih     = (const float*)d_in[8];
    const float* bhh     = (const float*)d_in[9];
    const float* alphap  = (const float*)d_in[10];
    const float* biasp   = (const float*)d_in[11];
    const float* unkscrp = (const float*)d_in[12];
    float* out = (float*)d_out;

    cudaFuncSetAttribute(mega, cudaFuncAttributeMaxDynamicSharedMemorySize, SMEM_BYTES);
    mega<<<GRID, TPB, SMEM_BYTES>>>(feature, A, protos, semb, sta, unkv,
                                    Wih, Whh, bih, bhh, alphap, biasp, unkscrp, out);
}

// round 9
// speedup vs baseline: 2.8790x; 2.8790x over previous
#include <cuda_runtime.h>
#include <cstdint>

#define NB 64
#define NC 512
#define NHW 768
#define NT 32
#define NPROTO 4000
#define NCLASS 4001
#define NG 1536
#define TPB 256
#define NSL 8
#define SMEM_BYTES (16896*4)

typedef unsigned long long ull;

// ---------------- device scratch ----------------
__device__ float g_C[NT * NB * NC];
__device__ float g_giC[NT * NB * NG];
__device__ float g_T[4032 * NG];
__device__ float g_Praw[NSL * NB * 4032];
__device__ float g_Pgh[NSL * NB * NG];
__device__ float g_h[NB * NC];
__device__ ull   g_amax[2][NB];
__device__ unsigned g_tick, g_barcnt, g_barsense;

struct __align__(16) U2 { ull lo, hi; };

static __device__ __forceinline__ ull ffma2(ull a, ull b, ull c) {
    ull d;
    asm("fma.rn.f32x2 %0, %1, %2, %3;" : "=l"(d) : "l"(a), "l"(b), "l"(c));
    return d;
}
static __device__ __forceinline__ float fin(ull v) {
    float2 f = *(float2*)&v;
    return f.x + f.y;
}
static __device__ __forceinline__ ull packkey(float s, int j) {
    unsigned u = __float_as_uint(s);
    u = (u & 0x80000000u) ? ~u : (u | 0x80000000u);
    return ((ull)u << 32) | (ull)(0xFFFFFFFFu - (unsigned)j);
}
static __device__ __forceinline__ void cpa16(unsigned dst, const float* src) {
    asm volatile("cp.async.cg.shared.global [%0],[%1],16;" :: "r"(dst), "l"(src));
}
static __device__ __forceinline__ void gridbar(unsigned& phase) {
    __syncthreads();
    if (threadIdx.x == 0) {
        phase += 1;
        unsigned old;
        asm volatile("atom.release.gpu.global.add.u32 %0,[%1],%2;"
                     : "=r"(old) : "l"(&g_barcnt), "r"(1u) : "memory");
        if (old == gridDim.x - 1u) {
            g_barcnt = 0u;
            asm volatile("st.release.gpu.global.u32 [%0],%1;"
                         :: "l"(&g_barsense), "r"(phase) : "memory");
        } else {
            unsigned v;
            do {
                __nanosleep(32);
                asm volatile("ld.acquire.gpu.global.u32 %0,[%1];"
                             : "=r"(v) : "l"(&g_barsense) : "memory");
            } while (v != phase);
        }
    }
    __syncthreads();
}
static __device__ __forceinline__ int grab(unsigned base, int tid, int* su) {
    __syncthreads();
    if (tid == 0) *su = (int)(atomicAdd(&g_tick, 1u) - base);
    __syncthreads();
    return *su;
}

// smem layout (floats): X buffers at 0 / 4352 (64 rows * 68); W buffers at 8704 / 12800
// W 64-row layout: even rows at +0, odd rows at +2048; pair p=r>>1: off (q*32+p)*4
#define LDX(buf, kk) do { _Pragma("unroll") for (int i_=0;i_<4;++i_){                  \
    int idx=tid+i_*256; int r=idx>>4, q=idx&15;                                        \
    cpa16(sb+((buf)*4352+r*68+4*q)*4, Xb+(size_t)r*xs+(kk)+4*q); } } while(0)
#define LDXP(buf, kk) do { _Pragma("unroll") for (int i_=0;i_<4;++i_){                 \
    int idx=tid+i_*256; int r=idx>>4, q=idx&15;                                        \
    cpa16(sb+((buf)*4352+r*68+4*q)*4, prow[r]+(kk)+4*q); } } while(0)
#define LDW64(buf, kk) do { _Pragma("unroll") for (int i_=0;i_<4;++i_){                \
    int idx=tid+i_*256; int r=idx>>4, q=idx&15; int row=j0+r; if(row>maxr)row=maxr;    \
    cpa16(sb+(8704+(buf)*4096+(r&1)*2048+(q*32+(r>>1))*4)*4,                           \
          Wb+(size_t)row*ws+(kk)+4*q); } } while(0)
#define LDW32(buf, kk) do { _Pragma("unroll") for (int i_=0;i_<2;++i_){                \
    int idx=tid+i_*256; int r=idx>>4, q=idx&15;                                        \
    cpa16(sb+(8704+(buf)*4096+(q*32+r)*4)*4, Wb+(size_t)r*ws+(kk)+4*q); } } while(0)
#define COMMIT() asm volatile("cp.async.commit_group;")
#define WAIT1()  asm volatile("cp.async.wait_group 1;")
#define WAIT0()  asm volatile("cp.async.wait_group 0;")

static __device__ __forceinline__ void core64(ull acc[8][2], const float* Xs,
                                              const U2* We, const U2* Wo,
                                              int lane, int b0) {
#pragma unroll 4
    for (int q = 0; q < 16; ++q) {
        U2 we = We[q * 32 + lane];
        U2 wo = Wo[q * 32 + lane];
#pragma unroll
        for (int r = 0; r < 8; ++r) {
            U2 xv = *(const U2*)(Xs + (b0 + r) * 68 + 4 * q);
            acc[r][0] = ffma2(xv.lo, we.lo, acc[r][0]);
            acc[r][0] = ffma2(xv.hi, we.hi, acc[r][0]);
            acc[r][1] = ffma2(xv.lo, wo.lo, acc[r][1]);
            acc[r][1] = ffma2(xv.hi, wo.hi, acc[r][1]);
        }
    }
}

// 64-row x 64-col unit, nch K-chunks of 64 starting at k00
static __device__ void gemm64(ull acc[8][2], const float* Xb, size_t xs,
                              const float* const* prow, const float* Wb, size_t ws,
                              int j0, int maxr, int nch, int k00,
                              int tid, unsigned sb, float* S) {
    const int lane = tid & 31, b0 = (tid >> 5) << 3;
#pragma unroll
    for (int r = 0; r < 8; ++r) { acc[r][0] = 0ull; acc[r][1] = 0ull; }
    if (prow) LDXP(0, k00); else LDX(0, k00);
    LDW64(0, k00); COMMIT();
    for (int c = 0; c < nch; ++c) {
        int buf = c & 1;
        if (c + 1 < nch) {
            int k = k00 + (c + 1) * 64;
            if (prow) LDXP(buf ^ 1, k); else LDX(buf ^ 1, k);
            LDW64(buf ^ 1, k); COMMIT(); WAIT1();
        } else WAIT0();
        __syncthreads();
        const U2* We = (const U2*)(S + 8704 + buf * 4096);
        core64(acc, S + buf * 4352, We, We + 512, lane, b0);
        __syncthreads();
    }
}

extern __shared__ float S[];

__global__ __launch_bounds__(TPB, 2)
void mega(const float* __restrict__ feat, const float* __restrict__ A,
          const float* __restrict__ protos, const float* __restrict__ semb,
          const float* __restrict__ sta, const float* __restrict__ unkv,
          const float* __restrict__ Wih, const float* __restrict__ Whh,
          const float* __restrict__ bih, const float* __restrict__ bhh,
          const float* __restrict__ alphap, const float* __restrict__ biasp,
          const float* __restrict__ unkscrp, float* __restrict__ out) {
    __shared__ const float* prow[64];
    __shared__ int su;
    const int tid = threadIdx.x, bid = blockIdx.x;
    const int gid = bid * TPB + tid, gth = gridDim.x * TPB;
    const int lane = tid & 31, b0 = (tid >> 5) << 3;
    unsigned sb = (unsigned)__cvta_generic_to_shared(S);
    unsigned phase = *(volatile unsigned*)&g_barsense;
    unsigned base = 0;
    const float alpha = *alphap, bias = *biasp, unkscr = *unkscrp;

    // -------- P0a: init + out_attns + einsum --------
    for (int i = gid; i < NB * NC; i += gth) g_h[i] = 0.f;
    if (gid < NB) g_amax[1][gid] = (ull)(0xFFFFFFFFu - 4001u);  // sentinel -> STA row
    {
        const float4* A4 = (const float4*)A;
        float4* O4 = (float4*)(out + (size_t)NB * NT * NCLASS);
        for (int i = gid; i < NB * NT * NHW / 4; i += gth) O4[i] = A4[i];
    }
    for (;;) {  // einsum: 512 units, 64 c-rows x 32 t-cols, K=768
        int u = grab(base, tid, &su);
        if (u >= 512) break;
        const int b = u & 63, c0 = (u >> 6) << 6;
        const float* Xb = feat + ((size_t)b * NC + c0) * NHW; size_t xs = NHW;
        const float* Wb = A + (size_t)b * NT * NHW; size_t ws = NHW;
        ull acc[8];
#pragma unroll
        for (int r = 0; r < 8; ++r) acc[r] = 0ull;
        LDX(0, 0); LDW32(0, 0); COMMIT();
        for (int c = 0; c < 12; ++c) {
            int buf = c & 1;
            if (c < 11) { LDX(buf ^ 1, (c + 1) * 64); LDW32(buf ^ 1, (c + 1) * 64); COMMIT(); WAIT1(); }
            else WAIT0();
            __syncthreads();
            const float* Xs = S + buf * 4352;
            const U2* Wq = (const U2*)(S + 8704 + buf * 4096);
#pragma unroll 4
            for (int q = 0; q < 16; ++q) {
                U2 wq = Wq[q * 32 + lane];
#pragma unroll
                for (int r = 0; r < 8; ++r) {
                    U2 xv = *(const U2*)(Xs + (b0 + r) * 68 + 4 * q);
                    acc[r] = ffma2(xv.lo, wq.lo, acc[r]);
                    acc[r] = ffma2(xv.hi, wq.hi, acc[r]);
                }
            }
            __syncthreads();
        }
#pragma unroll
        for (int r = 0; r < 8; ++r)
            g_C[(size_t)lane * NB * NC + (size_t)b * NC + c0 + b0 + r] = fin(acc[r]);
    }
    base += 512 + gridDim.x;
    gridbar(phase);

    // -------- P0b: giC (768 units) + T table (1512 units) --------
    for (;;) {
        int u = grab(base, tid, &su);
        if (u >= 2280) break;
        ull acc[8][2];
        if (u < 768) {
            const int m0 = (u & 31) << 6, j0 = (u >> 5) << 6;
            gemm64(acc, g_C + (size_t)m0 * NC, NC, 0, Wih, 1024, j0, NG - 1, 8, 0, tid, sb, S);
#pragma unroll
            for (int r = 0; r < 8; ++r)
                *(float2*)&g_giC[(size_t)(m0 + b0 + r) * NG + j0 + 2 * lane] =
                    make_float2(fin(acc[r][0]), fin(acc[r][1]));
        } else {
            const int u3 = u - 768;
            const int r0 = (u3 % 63) << 6, j0 = (u3 / 63) << 6;
            if (tid < 64) {
                int i = r0 + tid; if (i > NPROTO + 1) i = NPROTO + 1;
                prow[tid] = (i < NPROTO) ? semb + (size_t)i * NC : ((i == NPROTO) ? unkv : sta);
            }
            __syncthreads();
            gemm64(acc, 0, 0, prow, Wih + 512, 1024, j0, NG - 1, 8, 0, tid, sb, S);
#pragma unroll
            for (int r = 0; r < 8; ++r)
                *(float2*)&g_T[(size_t)(r0 + b0 + r) * NG + j0 + 2 * lane] =
                    make_float2(fin(acc[r][0]), fin(acc[r][1]));
        }
    }
    base += 2280 + gridDim.x;
    gridbar(phase);

    // -------- time loop: t = 0..NT (A: GEMMs, B: reduce+argmax, C: GRU) --------
    for (int t = 0; t <= NT; ++t) {
        const int rawC = (t >= 1) ? 63 * NSL : 0;
        const int ghC = (t < NT) ? 24 * NSL : 0;
        if (t >= 1 && bid == 0 && tid < NB) g_amax[(t - 1) & 1][tid] = 0ull;
        for (;;) {
            int u = grab(base, tid, &su);
            if (u >= rawC + ghC) break;
            ull acc[8][2];
            if (u < rawC) {
                const int ju = u % 63, sl = u / 63, j0 = ju << 6, k0 = sl << 6;
                gemm64(acc, g_h, NC, 0, protos, NC, j0, NPROTO - 1, 1, k0, tid, sb, S);
                float* P = g_Praw + (size_t)sl * NB * 4032;
#pragma unroll
                for (int r = 0; r < 8; ++r)
                    *(float2*)&P[(b0 + r) * 4032 + j0 + 2 * lane] =
                        make_float2(fin(acc[r][0]), fin(acc[r][1]));
            } else {
                const int u2 = u - rawC;
                const int ju = u2 % 24, sl = u2 / 24, j0 = ju << 6, k0 = sl << 6;
                gemm64(acc, g_h, NC, 0, Whh, NC, j0, NG - 1, 1, k0, tid, sb, S);
                float* P = g_Pgh + (size_t)sl * NB * NG;
#pragma unroll
                for (int r = 0; r < 8; ++r)
                    *(float2*)&P[(b0 + r) * NG + j0 + 2 * lane] =
                        make_float2(fin(acc[r][0]), fin(acc[r][1]));
            }
        }
        base += rawC + ghC + gridDim.x;
        gridbar(phase);

        if (t >= 1) {  // B: reduce raw(t-1), write scores, argmax
            const int tp = t - 1;
            for (int f = gid; f < NB * 4096; f += gth) {
                const int b = f >> 12, j = f & 4095;
                ull key = 0ull;
                if (j < NPROTO) {
                    float s = 0.f;
#pragma unroll
                    for (int sl = 0; sl < NSL; ++sl)
                        s += g_Praw[(size_t)sl * NB * 4032 + b * 4032 + j];
                    float sc = s * alpha + bias;
                    out[((size_t)b * NT + tp) * NCLASS + j] = sc;
                    key = packkey(sc, j);
                }
#pragma unroll
                for (int off = 16; off >= 1; off >>= 1) {
                    ull o = __shfl_xor_sync(0xFFFFFFFFu, key, off);
                    if (o > key) key = o;
                }
                if (lane == 0) atomicMax(&g_amax[tp & 1][b], key);
            }
            if (bid == 0 && tid < NB) {
                out[((size_t)tid * NT + tp) * NCLASS + NPROTO] = unkscr;
                atomicMax(&g_amax[tp & 1][tid], packkey(unkscr, NPROTO));
            }
        }
        gridbar(phase);

        if (t < NT && gid < NB * NC) {  // C: GRU pointwise
            const int b = gid >> 9, c = gid & 511;
            unsigned idx = 0xFFFFFFFFu - (unsigned)(g_amax[(t + 1) & 1][b] & 0xFFFFFFFFull);
            const float* Tr = g_T + (size_t)idx * NG;
            const float* Gi = g_giC + ((size_t)t * NB + b) * NG;
            float hr = 0.f, hz = 0.f, hn = 0.f;
#pragma unroll
            for (int sl = 0; sl < NSL; ++sl) {
                const float* P = g_Pgh + (size_t)sl * NB * NG + b * NG;
                hr += P[c]; hz += P[512 + c]; hn += P[1024 + c];
            }
            float ir = Gi[c] + Tr[c] + bih[c];
            float iz = Gi[512 + c] + Tr[512 + c] + bih[512 + c];
            float inn = Gi[1024 + c] + Tr[1024 + c] + bih[1024 + c];
            hr += bhh[c]; hz += bhh[512 + c]; hn += bhh[1024 + c];
            double r = 1.0 / (1.0 + exp(-(double)(ir + hr)));
            double z = 1.0 / (1.0 + exp(-(double)(iz + hz)));
            double n = tanh((double)inn + r * (double)hn);
            float hold = g_h[gid];
            g_h[gid] = (float)((1.0 - z) * n + z * (double)hold);
        }
        gridbar(phase);
    }
    if (bid == 0 && tid == 0) g_tick = 0u;  // reset for next graph replay
}

extern "C" void kernel_launch(void* const* d_in, const int* in_sizes, int n_in,
                              void* d_out, int out_size) {
    const float* feature = (const float*)d_in[0];
    const float* A       = (const float*)d_in[1];
    const float* protos  = (const float*)d_in[2];
    const float* semb    = (const float*)d_in[3];
    const float* sta     = (const float*)d_in[4];
    const float* unkv    = (const float*)d_in[5];
    const float* Wih     = (const float*)d_in[6];
    const float* Whh     = (const float*)d_in[7];
    const float* bih     = (const float*)d_in[8];
    const float* bhh     = (const float*)d_in[9];
    const float* alphap  = (const float*)d_in[10];
    const float* biasp   = (const float*)d_in[11];
    const float* unkscrp = (const float*)d_in[12];
    float* out = (float*)d_out;

    int dev = 0; cudaGetDevice(&dev);
    int sms = 148;
    cudaDeviceGetAttribute(&sms, cudaDevAttrMultiProcessorCount, dev);
    cudaFuncSetAttribute(mega, cudaFuncAttributeMaxDynamicSharedMemorySize, SMEM_BYTES);
    mega<<<2 * sms, TPB, SMEM_BYTES>>>(feature, A, protos, semb, sta, unkv,
                                       Wih, Whh, bih, bhh, alphap, biasp, unkscrp, out);
}